// round 5
// baseline (speedup 1.0000x reference)
#include <cuda_runtime.h>
#include <stdint.h>

// ---------------------------------------------------------------------------
// PairLoss:  result = ( sum_{gt<0.5} exp(p) * sum_{gt>0.5} exp(-p) - n_neg ) / 2
// Single fused kernel: grid-stride streaming reduction (HBM-bound, ~40us floor)
// + threadfence-reduction final combine in the last-arriving block.
// Deterministic (fixed-order fp64 final sum), graph-capturable,
// allocation-free (__device__ globals; counter self-resets each launch).
// ---------------------------------------------------------------------------

#define NBLOCKS 1184
#define NTHREADS 256

__device__ double g_part[3 * NBLOCKS];
__device__ unsigned int g_done = 0;   // self-resetting arrival counter

__device__ __forceinline__ void accum_one(float p, float g, float& s_neg,
                                          float& s_pos, float& cnt) {
    bool pos = g > 0.5f;
    float e = __expf(pos ? -p : p);
    if (pos) s_pos += e;
    else { s_neg += e; cnt += 1.0f; }
}

// Reduce three values across the block; results valid on (warp 0, lane 0).
template <typename T>
__device__ __forceinline__ void block_reduce3(T& a, T& b, T& c, T* sh) {
    int lane = threadIdx.x & 31;
    int warp = threadIdx.x >> 5;
    const int nw = NTHREADS / 32;

    #pragma unroll
    for (int off = 16; off > 0; off >>= 1) {
        a += __shfl_down_sync(0xffffffffu, a, off);
        b += __shfl_down_sync(0xffffffffu, b, off);
        c += __shfl_down_sync(0xffffffffu, c, off);
    }
    if (lane == 0) { sh[warp] = a; sh[nw + warp] = b; sh[2 * nw + warp] = c; }
    __syncthreads();
    if (warp == 0) {
        a = (lane < nw) ? sh[lane] : (T)0;
        b = (lane < nw) ? sh[nw + lane] : (T)0;
        c = (lane < nw) ? sh[2 * nw + lane] : (T)0;
        #pragma unroll
        for (int off = 16; off > 0; off >>= 1) {
            a += __shfl_down_sync(0xffffffffu, a, off);
            b += __shfl_down_sync(0xffffffffu, b, off);
            c += __shfl_down_sync(0xffffffffu, c, off);
        }
    }
}

__device__ __forceinline__ void epilogue(float s_neg, float s_pos, float cnt,
                                         float* __restrict__ out) {
    __shared__ float shf[3 * (NTHREADS / 32)];
    block_reduce3(s_neg, s_pos, cnt, shf);

    __shared__ bool s_last;
    if (threadIdx.x == 0) {
        g_part[blockIdx.x]               = (double)s_neg;
        g_part[NBLOCKS + blockIdx.x]     = (double)s_pos;
        g_part[2 * NBLOCKS + blockIdx.x] = (double)cnt;
        __threadfence();
        unsigned int prev = atomicAdd(&g_done, 1u);
        s_last = (prev == (unsigned int)(gridDim.x - 1));
    }
    __syncthreads();

    if (s_last) {
        __threadfence();  // acquire: all blocks' partials now visible
        double a = 0.0, b = 0.0, c = 0.0;
        for (int k = threadIdx.x; k < NBLOCKS; k += NTHREADS) {
            a += g_part[k];
            b += g_part[NBLOCKS + k];
            c += g_part[2 * NBLOCKS + k];
        }
        __shared__ double shd[3 * (NTHREADS / 32)];
        block_reduce3(a, b, c, shd);
        if (threadIdx.x == 0) {
            out[0] = (float)((a * b - c) * 0.5);
            g_done = 0;  // reset for next graph replay
        }
    }
}

__global__ void __launch_bounds__(NTHREADS)
pairloss_fused(const float4* __restrict__ p4, const float4* __restrict__ g4,
               const float* __restrict__ pred, const float* __restrict__ gt,
               int n, float* __restrict__ out) {
    float s_neg = 0.0f, s_pos = 0.0f, cnt = 0.0f;
    const int n4 = n >> 2;
    const int stride = gridDim.x * blockDim.x;
    int i = blockIdx.x * blockDim.x + threadIdx.x;

    // x2-unrolled grid-stride: 4 independent LDG.128 in flight per iteration.
    for (; i + stride < n4; i += 2 * stride) {
        float4 pa = p4[i];
        float4 ga = g4[i];
        float4 pb = p4[i + stride];
        float4 gb = g4[i + stride];
        accum_one(pa.x, ga.x, s_neg, s_pos, cnt);
        accum_one(pa.y, ga.y, s_neg, s_pos, cnt);
        accum_one(pa.z, ga.z, s_neg, s_pos, cnt);
        accum_one(pa.w, ga.w, s_neg, s_pos, cnt);
        accum_one(pb.x, gb.x, s_neg, s_pos, cnt);
        accum_one(pb.y, gb.y, s_neg, s_pos, cnt);
        accum_one(pb.z, gb.z, s_neg, s_pos, cnt);
        accum_one(pb.w, gb.w, s_neg, s_pos, cnt);
    }
    if (i < n4) {
        float4 p = p4[i];
        float4 g = g4[i];
        accum_one(p.x, g.x, s_neg, s_pos, cnt);
        accum_one(p.y, g.y, s_neg, s_pos, cnt);
        accum_one(p.z, g.z, s_neg, s_pos, cnt);
        accum_one(p.w, g.w, s_neg, s_pos, cnt);
    }
    // scalar tail (n % 4)
    for (int t = (n4 << 2) + blockIdx.x * blockDim.x + threadIdx.x; t < n;
         t += stride) {
        accum_one(pred[t], gt[t], s_neg, s_pos, cnt);
    }

    epilogue(s_neg, s_pos, cnt, out);
}

// Scalar fallback for unaligned inputs (not expected from the harness).
__global__ void __launch_bounds__(NTHREADS)
pairloss_fused_scalar(const float* __restrict__ pred,
                      const float* __restrict__ gt, int n,
                      float* __restrict__ out) {
    float s_neg = 0.0f, s_pos = 0.0f, cnt = 0.0f;
    int stride = gridDim.x * blockDim.x;
    for (int i = blockIdx.x * blockDim.x + threadIdx.x; i < n; i += stride)
        accum_one(pred[i], gt[i], s_neg, s_pos, cnt);

    epilogue(s_neg, s_pos, cnt, out);
}

extern "C" void kernel_launch(void* const* d_in, const int* in_sizes, int n_in,
                              void* d_out, int out_size) {
    const float* pred = (const float*)d_in[0];
    const float* gt   = (const float*)d_in[1];
    float* out = (float*)d_out;
    int n = in_sizes[0];

    bool aligned = (((uintptr_t)pred | (uintptr_t)gt) & 0xF) == 0;
    if (aligned) {
        pairloss_fused<<<NBLOCKS, NTHREADS>>>(
            (const float4*)pred, (const float4*)gt, pred, gt, n, out);
    } else {
        pairloss_fused_scalar<<<NBLOCKS, NTHREADS>>>(pred, gt, n, out);
    }
}

// round 6
// speedup vs baseline: 1.0401x; 1.0401x over previous
#include <cuda_runtime.h>
#include <stdint.h>

// ---------------------------------------------------------------------------
// PairLoss:  result = ( sum_{gt<0.5} exp(p) * sum_{gt>0.5} exp(-p) - n_neg ) / 2
// Single fused kernel: grid-stride float4 streaming reduction (HBM-bound)
// + threadfence-reduction final combine in the last-arriving block.
// x1 unroll on purpose: MLP_p1=2 stays below the cross-CTA L1tex-queue
// contention knee (oe*MLP_p1 <= 16), minimizing CTA completion spread, which
// the last-block epilogue is directly exposed to.
// Deterministic (fixed-order fp64 final sum), graph-capturable, alloc-free.
// ---------------------------------------------------------------------------

#define NBLOCKS 1184
#define NTHREADS 256

__device__ double g_part[3 * NBLOCKS];
__device__ unsigned int g_done = 0;   // self-resetting arrival counter

__device__ __forceinline__ void accum_one(float p, float g, float& s_neg,
                                          float& s_pos, float& cnt) {
    bool pos = g > 0.5f;
    float e = __expf(pos ? -p : p);
    if (pos) s_pos += e;
    else { s_neg += e; cnt += 1.0f; }
}

// Reduce three values across the block; results valid on (warp 0, lane 0).
template <typename T>
__device__ __forceinline__ void block_reduce3(T& a, T& b, T& c, T* sh) {
    int lane = threadIdx.x & 31;
    int warp = threadIdx.x >> 5;
    const int nw = NTHREADS / 32;

    #pragma unroll
    for (int off = 16; off > 0; off >>= 1) {
        a += __shfl_down_sync(0xffffffffu, a, off);
        b += __shfl_down_sync(0xffffffffu, b, off);
        c += __shfl_down_sync(0xffffffffu, c, off);
    }
    if (lane == 0) { sh[warp] = a; sh[nw + warp] = b; sh[2 * nw + warp] = c; }
    __syncthreads();
    if (warp == 0) {
        a = (lane < nw) ? sh[lane] : (T)0;
        b = (lane < nw) ? sh[nw + lane] : (T)0;
        c = (lane < nw) ? sh[2 * nw + lane] : (T)0;
        #pragma unroll
        for (int off = 16; off > 0; off >>= 1) {
            a += __shfl_down_sync(0xffffffffu, a, off);
            b += __shfl_down_sync(0xffffffffu, b, off);
            c += __shfl_down_sync(0xffffffffu, c, off);
        }
    }
}

__device__ __forceinline__ void epilogue(float s_neg, float s_pos, float cnt,
                                         float* __restrict__ out) {
    __shared__ float shf[3 * (NTHREADS / 32)];
    block_reduce3(s_neg, s_pos, cnt, shf);

    __shared__ bool s_last;
    if (threadIdx.x == 0) {
        g_part[blockIdx.x]               = (double)s_neg;
        g_part[NBLOCKS + blockIdx.x]     = (double)s_pos;
        g_part[2 * NBLOCKS + blockIdx.x] = (double)cnt;
        __threadfence();
        unsigned int prev = atomicAdd(&g_done, 1u);
        s_last = (prev == (unsigned int)(gridDim.x - 1));
    }
    __syncthreads();

    if (s_last) {
        __threadfence();  // acquire: all blocks' partials now visible
        double a = 0.0, b = 0.0, c = 0.0;
        for (int k = threadIdx.x; k < NBLOCKS; k += NTHREADS) {
            a += g_part[k];
            b += g_part[NBLOCKS + k];
            c += g_part[2 * NBLOCKS + k];
        }
        __shared__ double shd[3 * (NTHREADS / 32)];
        block_reduce3(a, b, c, shd);
        if (threadIdx.x == 0) {
            out[0] = (float)((a * b - c) * 0.5);
            g_done = 0;  // reset for next graph replay
        }
    }
}

__global__ void __launch_bounds__(NTHREADS)
pairloss_fused(const float4* __restrict__ p4, const float4* __restrict__ g4,
               const float* __restrict__ pred, const float* __restrict__ gt,
               int n, float* __restrict__ out) {
    float s_neg = 0.0f, s_pos = 0.0f, cnt = 0.0f;
    const int n4 = n >> 2;
    const int stride = gridDim.x * blockDim.x;

    // x1 grid-stride: exactly 2 front-batched LDG.128 per iteration.
    // Streaming (.cs) loads: data is 2x128MB, pure one-touch -> bypass-ish L2.
    for (int i = blockIdx.x * blockDim.x + threadIdx.x; i < n4; i += stride) {
        float4 p = __ldcs(p4 + i);
        float4 g = __ldcs(g4 + i);
        accum_one(p.x, g.x, s_neg, s_pos, cnt);
        accum_one(p.y, g.y, s_neg, s_pos, cnt);
        accum_one(p.z, g.z, s_neg, s_pos, cnt);
        accum_one(p.w, g.w, s_neg, s_pos, cnt);
    }
    // scalar tail (n % 4)
    for (int t = (n4 << 2) + blockIdx.x * blockDim.x + threadIdx.x; t < n;
         t += stride) {
        accum_one(__ldcs(pred + t), __ldcs(gt + t), s_neg, s_pos, cnt);
    }

    epilogue(s_neg, s_pos, cnt, out);
}

// Scalar fallback for unaligned inputs (not expected from the harness).
__global__ void __launch_bounds__(NTHREADS)
pairloss_fused_scalar(const float* __restrict__ pred,
                      const float* __restrict__ gt, int n,
                      float* __restrict__ out) {
    float s_neg = 0.0f, s_pos = 0.0f, cnt = 0.0f;
    int stride = gridDim.x * blockDim.x;
    for (int i = blockIdx.x * blockDim.x + threadIdx.x; i < n; i += stride)
        accum_one(__ldcs(pred + i), __ldcs(gt + i), s_neg, s_pos, cnt);

    epilogue(s_neg, s_pos, cnt, out);
}

extern "C" void kernel_launch(void* const* d_in, const int* in_sizes, int n_in,
                              void* d_out, int out_size) {
    const float* pred = (const float*)d_in[0];
    const float* gt   = (const float*)d_in[1];
    float* out = (float*)d_out;
    int n = in_sizes[0];

    bool aligned = (((uintptr_t)pred | (uintptr_t)gt) & 0xF) == 0;
    if (aligned) {
        pairloss_fused<<<NBLOCKS, NTHREADS>>>(
            (const float4*)pred, (const float4*)gt, pred, gt, n, out);
    } else {
        pairloss_fused_scalar<<<NBLOCKS, NTHREADS>>>(pred, gt, n, out);
    }
}